// round 10
// baseline (speedup 1.0000x reference)
#include <cuda_runtime.h>
#include <cuda_bf16.h>
#include <math.h>

#define NUM_LEVELS 16
#define TABLE_SIZE (1u << 19)
#define TSAMP 192
#define PTS 128            // points per block
#define NTHREADS 256
#define FS4 20             // feats row stride in uint4: 20%8==4 -> (16r+4c)%32 bijective/octet
#define WS4 66             // W row stride in uint4:   66%8==2 -> (8c+4r)%32 bijective/octet

struct LevelParams {
    float scale[NUM_LEVELS];
    int   res[NUM_LEVELS];
    unsigned hashed_mask;
};

__device__ __forceinline__ float softplus10(float v) {
    float y = 10.0f * v;
    float t = __expf(-fabsf(y));
    return (fmaxf(y, 0.0f) + __logf(1.0f + t)) * 0.1f;
}

__device__ __forceinline__ unsigned pack_bf16x2(float lo_val, float hi_val) {
    // lo_val -> low 16 bits (element k), hi_val -> high 16 bits (element k+1)
    unsigned r;
    asm("cvt.rn.bf16x2.f32 %0, %1, %2;" : "=r"(r) : "f"(hi_val), "f"(lo_val));
    return r;
}

#define MMA_BF16(C, A0, A1, A2, A3, B0, B1)                                    \
    asm volatile(                                                              \
        "mma.sync.aligned.m16n8k16.row.col.f32.bf16.bf16.f32 "                 \
        "{%0,%1,%2,%3}, {%4,%5,%6,%7}, {%8,%9}, {%0,%1,%2,%3};"                \
        : "+f"(C[0]), "+f"(C[1]), "+f"(C[2]), "+f"(C[3])                       \
        : "r"(A0), "r"(A1), "r"(A2), "r"(A3), "r"(B0), "r"(B1));

// gather + bilinear interp for one level -> f0..f3
__device__ __forceinline__ void gather_level(
    int l, float ux, float uy, const LevelParams& lp, const float4* __restrict__ emb,
    float& f0, float& f1, float& f2, float& f3)
{
    float s = lp.scale[l];
    float posx = ux * s + 0.5f;
    float posy = uy * s + 0.5f;
    float pfx = floorf(posx), pfy = floorf(posy);
    float frx = posx - pfx,   fry = posy - pfy;
    int ix = (int)pfx, iy = (int)pfy;

    unsigned i00, i01, i10, i11;
    if ((lp.hashed_mask >> l) & 1u) {
        unsigned hy0 = (unsigned)iy * 2654435761u;
        unsigned hy1 = (unsigned)(iy + 1) * 2654435761u;
        i00 = ((unsigned)ix       ^ hy0) & (TABLE_SIZE - 1u);
        i01 = ((unsigned)ix       ^ hy1) & (TABLE_SIZE - 1u);
        i10 = ((unsigned)(ix + 1) ^ hy0) & (TABLE_SIZE - 1u);
        i11 = ((unsigned)(ix + 1) ^ hy1) & (TABLE_SIZE - 1u);
    } else {
        int res = lp.res[l];
        i00 = (unsigned)(iy * res + ix);
        i01 = i00 + (unsigned)res;
        i10 = i00 + 1u;
        i11 = i01 + 1u;
    }

    const float4* tab = emb + (size_t)l * TABLE_SIZE;
    float4 c00 = __ldg(tab + i00);
    float4 c01 = __ldg(tab + i01);
    float4 c10 = __ldg(tab + i10);
    float4 c11 = __ldg(tab + i11);

    float w00 = (1.0f - frx) * (1.0f - fry);
    float w01 = (1.0f - frx) * fry;
    float w10 = frx * (1.0f - fry);
    float w11 = frx * fry;

    f0 = ((c00.x * w00 + c01.x * w01) + c10.x * w10) + c11.x * w11;
    f1 = ((c00.y * w00 + c01.y * w01) + c10.y * w10) + c11.y * w11;
    f2 = ((c00.z * w00 + c01.z * w01) + c10.z * w10) + c11.z * w11;
    f3 = ((c00.w * w00 + c01.w * w01) + c10.w * w10) + c11.w * w11;
}

__global__ __launch_bounds__(NTHREADS, 3)
void nerf_fused(const float* __restrict__ x,
                const float4* __restrict__ emb,
                const float* __restrict__ W0,
                const float* __restrict__ b0,
                const float* __restrict__ W1,
                const float* __restrict__ b1,
                float* __restrict__ out,
                LevelParams lp)
{
    extern __shared__ unsigned smu[];
    uint4* sF4 = (uint4*)smu;                  // [PTS][FS4]   packed feats
    uint4* sB4 = sF4 + PTS * FS4;              // [16][WS4]    packed W0
    float* sb0 = (float*)(sB4 + 16 * WS4);     // [64]
    float* sW1 = sb0 + 64;                     // [64]
    float* sb1 = sW1 + 64;                     // [1]

    const int tid = threadIdx.x;

    // ---- W0 -> packed uint4 {hi(c),lo(c),hi(c+4),lo(c+4)} per (kk,c,n) ----
    for (int e = tid; e < 1024; e += NTHREADS) {
        int row = e >> 6, n = e & 63;           // row = kk*4 + c
        int kk = row >> 2, cc = row & 3;
        int k2a = kk * 8 + cc;                  // k-pair indices
        int k2b = k2a + 4;
        float wa0 = W0[(2 * k2a) * 64 + n];
        float wa1 = W0[(2 * k2a + 1) * 64 + n];
        float wb0 = W0[(2 * k2b) * 64 + n];
        float wb1 = W0[(2 * k2b + 1) * 64 + n];
        float ha0 = __bfloat162float(__float2bfloat16(wa0));
        float ha1 = __bfloat162float(__float2bfloat16(wa1));
        float hb0 = __bfloat162float(__float2bfloat16(wb0));
        float hb1 = __bfloat162float(__float2bfloat16(wb1));
        uint4 v;
        v.x = pack_bf16x2(ha0, ha1);
        v.y = pack_bf16x2(wa0 - ha0, wa1 - ha1);
        v.z = pack_bf16x2(hb0, hb1);
        v.w = pack_bf16x2(wb0 - hb0, wb1 - hb1);
        sB4[row * WS4 + n] = v;
    }
    if (tid < 64) { sb0[tid] = b0[tid]; sW1[tid] = W1[tid]; }
    if (tid == 0) { sb1[0] = b1[0]; }

    // ---- Phase 1: gather; 2 threads/point; level pairs (4j+half, 4j+2+half) ----
    const int pt   = tid & (PTS - 1);
    const int half = tid >> 7;
    const int p    = blockIdx.x * PTS + pt;
    const int ray  = p / TSAMP;
    const int t    = p - ray * TSAMP;

    const float2* xr = (const float2*)(x + (size_t)ray * (TSAMP * 2));
    float2 o  = xr[0];
    float2 en = xr[TSAMP - 1];
    float dxr = en.x - o.x, dyr = en.y - o.y;
    float nrm = sqrtf(dxr * dxr + dyr * dyr);
    dxr /= nrm; dyr /= nrm;

    const float step = 2.0f / 191.0f;
    float z  = step * (float)t;
    float ux = (fminf(fmaxf(o.x + dxr * z, -1.0f), 1.0f) + 1.0f) * 0.5f;
    float uy = (fminf(fmaxf(o.y + dyr * z, -1.0f), 1.0f) + 1.0f) * 0.5f;

    uint4* f_row = sF4 + pt * FS4;
    #pragma unroll
    for (int j = 0; j < 4; ++j) {
        int la = 4 * j + half;                  // fills .xy (c-group b=0)
        int lb = la + 2;                        // fills .zw (c-group b=1)
        float fa0, fa1, fa2, fa3, fb0, fb1, fb2, fb3;
        gather_level(la, ux, uy, lp, emb, fa0, fa1, fa2, fa3);
        gather_level(lb, ux, uy, lp, emb, fb0, fb1, fb2, fb3);

        float ha0 = __bfloat162float(__float2bfloat16(fa0));
        float ha1 = __bfloat162float(__float2bfloat16(fa1));
        float ha2 = __bfloat162float(__float2bfloat16(fa2));
        float ha3 = __bfloat162float(__float2bfloat16(fa3));
        float hb0 = __bfloat162float(__float2bfloat16(fb0));
        float hb1 = __bfloat162float(__float2bfloat16(fb1));
        float hb2 = __bfloat162float(__float2bfloat16(fb2));
        float hb3 = __bfloat162float(__float2bfloat16(fb3));

        uint4 v0, v1;
        v0.x = pack_bf16x2(ha0, ha1);
        v0.y = pack_bf16x2(fa0 - ha0, fa1 - ha1);
        v0.z = pack_bf16x2(hb0, hb1);
        v0.w = pack_bf16x2(fb0 - hb0, fb1 - hb1);
        v1.x = pack_bf16x2(ha2, ha3);
        v1.y = pack_bf16x2(fa2 - ha2, fa3 - ha3);
        v1.z = pack_bf16x2(hb2, hb3);
        v1.w = pack_bf16x2(fb2 - hb2, fb3 - hb3);

        int e0 = j * 4 + 2 * half;              // (kk=j, c=2*half)
        f_row[e0]     = v0;
        f_row[e0 + 1] = v1;
    }

    __syncthreads();

    // ---- Phase 2: per-warp m16n8k16 bf16 GEMM, 3-pass split, all LDS.128 ----
    const int warp = tid >> 5;
    const int lane = tid & 31;
    const int r = lane >> 2;
    const int c = lane & 3;

    const uint4* Ab = sF4 + (warp * 16) * FS4;
    float sig0 = 0.f, sig1 = 0.f;

    #pragma unroll
    for (int ch = 0; ch < 2; ++ch) {
        float C[4][4];
        #pragma unroll
        for (int nt = 0; nt < 4; ++nt) {        // fold b0 into accumulator init
            int col0 = ch * 32 + nt * 8 + 2 * c;
            float ba = sb0[col0], bb = sb0[col0 + 1];
            C[nt][0] = ba; C[nt][1] = bb; C[nt][2] = ba; C[nt][3] = bb;
        }

        #pragma unroll
        for (int kk = 0; kk < 4; ++kk) {
            int e = kk * 4 + c;
            uint4 A0 = Ab[r * FS4 + e];         // {a0hi, a0lo, a2hi, a2lo}
            uint4 A1 = Ab[(r + 8) * FS4 + e];   // {a1hi, a1lo, a3hi, a3lo}

            const uint4* Brow = sB4 + e * WS4 + ch * 32;
            #pragma unroll
            for (int nt = 0; nt < 4; ++nt) {
                uint4 B = Brow[nt * 8 + r];     // {b0hi, b0lo, b1hi, b1lo}
                MMA_BF16(C[nt], A0.x, A1.x, A0.z, A1.z, B.x, B.z);  // hi*hi
                MMA_BF16(C[nt], A0.x, A1.x, A0.z, A1.z, B.y, B.w);  // hi*lo
                MMA_BF16(C[nt], A0.y, A1.y, A0.w, A1.w, B.x, B.z);  // lo*hi
            }
        }

        // partial epilogue for this column half
        #pragma unroll
        for (int nt = 0; nt < 4; ++nt) {
            int col0 = ch * 32 + nt * 8 + 2 * c;
            float w1a = sW1[col0], w1b = sW1[col0 + 1];
            sig0 += softplus10(C[nt][0]) * w1a;
            sig0 += softplus10(C[nt][1]) * w1b;
            sig1 += softplus10(C[nt][2]) * w1a;
            sig1 += softplus10(C[nt][3]) * w1b;
        }
    }

    sig0 += __shfl_xor_sync(0xffffffffu, sig0, 1);
    sig0 += __shfl_xor_sync(0xffffffffu, sig0, 2);
    sig1 += __shfl_xor_sync(0xffffffffu, sig1, 1);
    sig1 += __shfl_xor_sync(0xffffffffu, sig1, 2);

    if (c == 0) {
        float b1v = sb1[0];
        const float step2 = 2.0f / 191.0f;
        #pragma unroll
        for (int hrow = 0; hrow < 2; ++hrow) {
            int local = warp * 16 + r + hrow * 8;
            int pp = blockIdx.x * PTS + local;
            int rr = pp / TSAMP;
            int tt = pp - rr * TSAMP;
            float sigv  = (hrow == 0) ? sig0 : sig1;
            float sigma = softplus10(b1v + sigv);
            float zt  = step2 * (float)tt;
            float zt1 = step2 * (float)(tt - 1);
            float delta = (tt == 0) ? (1.0f / 192.0f) : (zt - zt1);
            out[pp] = delta * sigma;
        }
    }
}

extern "C" void kernel_launch(void* const* d_in, const int* in_sizes, int n_in,
                              void* d_out, int out_size) {
    const float* x   = (const float*)d_in[0];   // [4,2048,192,2]
    const float* emb = (const float*)d_in[1];   // [16, 524288, 4]
    const float* W0  = (const float*)d_in[2];   // [64,64]
    const float* b0  = (const float*)d_in[3];   // [64]
    const float* W1  = (const float*)d_in[4];   // [64,1]
    const float* b1  = (const float*)d_in[5];   // [1]
    float* out = (float*)d_out;

    LevelParams lp;
    const double b = exp((log(2048.0) - log(2.0)) / 15.0);
    unsigned mask = 0;
    for (int l = 0; l < NUM_LEVELS; ++l) {
        double s = 2.0 * pow(b, (double)l) - 1.0;
        lp.scale[l] = (float)s;
        int res = (int)ceil(s) + 1;
        lp.res[l] = res;
        if ((long long)res * (long long)res > (long long)TABLE_SIZE)
            mask |= (1u << l);
    }
    lp.hashed_mask = mask;

    const int smem_bytes = (PTS * FS4 + 16 * WS4) * 16 + (64 + 64 + 4) * 4;
    static int attr_set = 0;
    if (!attr_set) {
        cudaFuncSetAttribute(nerf_fused,
                             cudaFuncAttributeMaxDynamicSharedMemorySize,
                             smem_bytes);
        attr_set = 1;
    }

    int n_points = in_sizes[0] / 2;             // 1,572,864
    int n_blocks = n_points / PTS;              // 12288
    nerf_fused<<<n_blocks, NTHREADS, smem_bytes>>>(x, (const float4*)emb,
                                                   W0, b0, W1, b1, out, lp);
}